// round 1
// baseline (speedup 1.0000x reference)
#include <cuda_runtime.h>
#include <cstdint>
#include <cstddef>

#define MAXN 100000
#define MAXE 1600000

// ---------------- device scratch (static, no allocation) ----------------
__device__ float g_T[(size_t)MAXN * 128];   // GEMM output, pre-scaled by dinv[row]
__device__ float g_Y[(size_t)MAXN * 128];   // layer output / next layer input
__device__ float g_dinv[MAXN];
__device__ int   g_cnt[MAXN];
__device__ int   g_rowptr[MAXN + 1];
__device__ int   g_cursor[MAXN];
__device__ int   g_col[MAXE];

// ---------------- CSR build ----------------
__global__ void k_zero(int* __restrict__ p, int n) {
    int i = blockIdx.x * blockDim.x + threadIdx.x;
    if (i < n) p[i] = 0;
}

__global__ void k_count(const int* __restrict__ dst, int* __restrict__ cnt, int e) {
    int i = blockIdx.x * blockDim.x + threadIdx.x;
    if (i < e) atomicAdd(&cnt[dst[i]], 1);
}

// single-block exclusive scan over counts; also writes cursor copy and dinv
__global__ void k_scan(const int* __restrict__ cnt, int* __restrict__ rowptr,
                       int* __restrict__ cursor, float* __restrict__ dinv, int n) {
    __shared__ int sums[1024];
    int t = threadIdx.x;
    int ch = (n + 1023) / 1024;
    int beg = t * ch;
    int end = min(beg + ch, n);
    int s = 0;
    for (int i = beg; i < end; i++) s += cnt[i];
    sums[t] = s;
    __syncthreads();
    for (int off = 1; off < 1024; off <<= 1) {
        int v = (t >= off) ? sums[t - off] : 0;
        __syncthreads();
        sums[t] += v;
        __syncthreads();
    }
    int run = (t > 0) ? sums[t - 1] : 0;
    for (int i = beg; i < end; i++) {
        int c = cnt[i];
        rowptr[i] = run;
        cursor[i] = run;
        dinv[i] = rsqrtf((float)(c + 1));   // +1 self loop; always >= 1
        run += c;
    }
    if (t == 1023) rowptr[n] = sums[1023];
}

__global__ void k_fill(const int* __restrict__ src, const int* __restrict__ dst,
                       int* __restrict__ cursor, int* __restrict__ col, int e) {
    int i = blockIdx.x * blockDim.x + threadIdx.x;
    if (i < e) {
        int p = atomicAdd(&cursor[dst[i]], 1);
        col[p] = src[i];
    }
}

// ---------------- packed dual-fp32 helpers ----------------
__device__ __forceinline__ void fma2(unsigned long long& d,
                                     unsigned long long a, unsigned long long b) {
    asm("fma.rn.f32x2 %0, %1, %2, %0;" : "+l"(d) : "l"(a), "l"(b));
}
__device__ __forceinline__ float2 unpack2(unsigned long long v) {
    float2 r;
    asm("mov.b64 {%0, %1}, %2;" : "=f"(r.x), "=f"(r.y) : "l"(v));
    return r;
}

// ---------------- GEMM:  T[r][c] = dinv[r] * sum_k X[r][k] * W[k][c] ----------------
// block tile: 128 rows x OUT cols, 128 threads.
// thread tile: 8 rows x (OUT/8) cols as f32x2 column pairs.
// A stored duplicated (x,x) as float2 in smem -> inner loop is LDS.64 + FFMA2 only.
template <int OUT>
__global__ void __launch_bounds__(128)
k_gemm(const float* __restrict__ X, const float* __restrict__ W,
       const float* __restrict__ dinv, float* __restrict__ T, int n) {
    constexpr int KC = 32;
    constexpr int NJ = OUT / 16;   // f32x2 pairs per thread (8 for OUT=128, 4 for OUT=64)
    __shared__ __align__(16) float2 As[128 * KC];   // 32 KB, duplicated A values
    __shared__ __align__(16) float  Ws[KC * OUT];   // 16 KB (OUT=128) / 8 KB

    int tid = threadIdx.x;
    int tx = tid & 7;    // 8 column groups
    int ty = tid >> 3;   // 16 row groups (8 rows each)
    int rb = blockIdx.x * 128;

    unsigned long long acc[8][NJ];
#pragma unroll
    for (int i = 0; i < 8; i++)
#pragma unroll
        for (int j = 0; j < NJ; j++) acc[i][j] = 0ull;

    for (int kc = 0; kc < 128; kc += KC) {
        // load A tile (128 x 32), duplicating each value into float2
        {
            int c4 = tid & 7;      // 8 float4 per row
            int r0 = tid >> 3;     // 16 rows per pass
#pragma unroll
            for (int p = 0; p < 8; p++) {
                int row = r0 + p * 16;
                int g = rb + row;
                float4 v = make_float4(0.f, 0.f, 0.f, 0.f);
                if (g < n) v = *(const float4*)(X + (size_t)g * 128 + kc + c4 * 4);
                float2* d = As + row * KC + c4 * 4;
                d[0] = make_float2(v.x, v.x);
                d[1] = make_float2(v.y, v.y);
                d[2] = make_float2(v.z, v.z);
                d[3] = make_float2(v.w, v.w);
            }
        }
        // load W tile (KC x OUT), contiguous
        {
            constexpr int NF4 = KC * OUT / 4;
#pragma unroll
            for (int i = tid; i < NF4; i += 128)
                *(float4*)(Ws + (size_t)i * 4) = *(const float4*)(W + (size_t)kc * OUT + (size_t)i * 4);
        }
        __syncthreads();

#pragma unroll 8
        for (int k = 0; k < KC; k++) {
            unsigned long long a[8], w[NJ];
#pragma unroll
            for (int i = 0; i < 8; i++)
                a[i] = *(const unsigned long long*)(As + (ty * 8 + i) * KC + k);
#pragma unroll
            for (int j = 0; j < NJ; j++)
                w[j] = *(const unsigned long long*)(Ws + k * OUT + 2 * tx + 16 * j);
#pragma unroll
            for (int i = 0; i < 8; i++)
#pragma unroll
                for (int j = 0; j < NJ; j++)
                    fma2(acc[i][j], a[i], w[j]);
        }
        __syncthreads();
    }

#pragma unroll
    for (int i = 0; i < 8; i++) {
        int row = rb + ty * 8 + i;
        if (row < n) {
            float sc = dinv[row];
#pragma unroll
            for (int j = 0; j < NJ; j++) {
                float2 v = unpack2(acc[i][j]);
                v.x *= sc; v.y *= sc;
                *(float2*)(T + (size_t)row * OUT + 2 * tx + 16 * j) = v;
            }
        }
    }
}

// ---------------- aggregation:  Y[d] = act( dinv[d]*(T[d] + sum_{s in N(d)} T[s]) + b ) ----
// one warp per destination node; lane owns C/32 contiguous columns.
template <int C, bool RELU>
__global__ void __launch_bounds__(256)
k_agg(const float* __restrict__ T, const float* __restrict__ bias,
      const float* __restrict__ dinv, const int* __restrict__ rowptr,
      const int* __restrict__ col, float* __restrict__ Y, int n) {
    constexpr int V = C / 32;   // 4 or 2
    int w = (int)((blockIdx.x * 256 + threadIdx.x) >> 5);
    if (w >= n) return;
    int lane = threadIdx.x & 31;

    float acc[V];
    {
        const float* p = T + (size_t)w * C + lane * V;
        if (V == 4) {
            float4 t = *(const float4*)p;
            acc[0] = t.x; acc[1] = t.y; acc[2] = t.z; acc[3] = t.w;
        } else {
            float2 t = *(const float2*)p;
            acc[0] = t.x; acc[1] = t.y;
        }
    }

    int e = rowptr[w];
    int e1 = rowptr[w + 1];
    while (e < e1) {
        int m = min(32, e1 - e);
        int sidx = (lane < m) ? col[e + lane] : 0;
#pragma unroll 1
        for (int j = 0; j < m; j++) {
            int s = __shfl_sync(0xffffffffu, sidx, j);
            const float* p = T + (size_t)s * C + lane * V;
            if (V == 4) {
                float4 t = *(const float4*)p;
                acc[0] += t.x; acc[1] += t.y; acc[2] += t.z; acc[3] += t.w;
            } else {
                float2 t = *(const float2*)p;
                acc[0] += t.x; acc[1] += t.y;
            }
        }
        e += m;
    }

    float sc = dinv[w];
    float o[V];
    {
        const float* bp = bias + lane * V;
        if (V == 4) {
            float4 b = *(const float4*)bp;
            o[0] = fmaf(acc[0], sc, b.x);
            o[1] = fmaf(acc[1], sc, b.y);
            o[2] = fmaf(acc[2], sc, b.z);
            o[3] = fmaf(acc[3], sc, b.w);
        } else {
            float2 b = *(const float2*)bp;
            o[0] = fmaf(acc[0], sc, b.x);
            o[1] = fmaf(acc[1], sc, b.y);
        }
    }
    if (RELU) {
#pragma unroll
        for (int v = 0; v < V; v++) o[v] = fmaxf(o[v], 0.0f);
    }
    {
        float* p = Y + (size_t)w * C + lane * V;
        if (V == 4) *(float4*)p = make_float4(o[0], o[1], o[2], o[3]);
        else        *(float2*)p = make_float2(o[0], o[1]);
    }
}

// ---------------- launcher ----------------
extern "C" void kernel_launch(void* const* d_in, const int* in_sizes, int n_in,
                              void* d_out, int out_size) {
    const float* x  = (const float*)d_in[0];
    const int*   ei = (const int*)d_in[1];
    const float* W0 = (const float*)d_in[2];
    const float* b0 = (const float*)d_in[3];
    const float* W1 = (const float*)d_in[4];
    const float* b1 = (const float*)d_in[5];
    const float* W2 = (const float*)d_in[6];
    const float* b2 = (const float*)d_in[7];
    const float* W3 = (const float*)d_in[8];
    const float* b3 = (const float*)d_in[9];

    int N = in_sizes[0] / 128;
    int E = in_sizes[1] / 2;
    const int* src = ei;
    const int* dst = ei + E;

    float *T, *Y, *dinv;
    int *cnt, *rowptr, *cursor, *colx;
    cudaGetSymbolAddress((void**)&T, g_T);
    cudaGetSymbolAddress((void**)&Y, g_Y);
    cudaGetSymbolAddress((void**)&dinv, g_dinv);
    cudaGetSymbolAddress((void**)&cnt, g_cnt);
    cudaGetSymbolAddress((void**)&rowptr, g_rowptr);
    cudaGetSymbolAddress((void**)&cursor, g_cursor);
    cudaGetSymbolAddress((void**)&colx, g_col);

    // CSR build (per call; graph-capturable, deterministic work)
    k_zero <<<(N + 255) / 256, 256>>>(cnt, N);
    k_count<<<(E + 255) / 256, 256>>>(dst, cnt, E);
    k_scan <<<1, 1024>>>(cnt, rowptr, cursor, dinv, N);
    k_fill <<<(E + 255) / 256, 256>>>(src, dst, cursor, colx, E);

    int gg = (N + 127) / 128;
    int ga = (N + 7) / 8;

    // layer 0: GCNConv(D=128 -> H=128) + ReLU
    k_gemm<128><<<gg, 128>>>(x, W0, dinv, T, N);
    k_agg<128, true><<<ga, 256>>>(T, b0, dinv, rowptr, colx, Y, N);
    // layer 1
    k_gemm<128><<<gg, 128>>>(Y, W1, dinv, T, N);
    k_agg<128, true><<<ga, 256>>>(T, b1, dinv, rowptr, colx, Y, N);
    // layer 2
    k_gemm<128><<<gg, 128>>>(Y, W2, dinv, T, N);
    k_agg<128, true><<<ga, 256>>>(T, b2, dinv, rowptr, colx, Y, N);
    // layer 3: GCNConv(H=128 -> O=64), no activation, write d_out
    k_gemm<64><<<gg, 128>>>(Y, W3, dinv, T, N);
    k_agg<64, false><<<ga, 256>>>(T, b3, dinv, rowptr, colx, (float*)d_out, N);
}

// round 2
// speedup vs baseline: 1.4999x; 1.4999x over previous
#include <cuda_runtime.h>
#include <cstdint>
#include <cstddef>

#define MAXN 100000
#define MAXE 1600000

// ---------------- device scratch (static, no allocation) ----------------
__device__ float g_T[(size_t)MAXN * 128];   // GEMM output, pre-scaled by dinv[row]
__device__ float g_Y[(size_t)MAXN * 128];   // layer output / next layer input
__device__ float g_dinv[MAXN];
__device__ int   g_cnt[MAXN];
__device__ int   g_rowptr[MAXN + 1];
__device__ int   g_cursor[MAXN];
__device__ int   g_col[MAXE];
__device__ int   g_part[256];               // block partial sums for scan

// ---------------- CSR build ----------------
__global__ void k_zero(int* __restrict__ p, int n) {
    int i = blockIdx.x * blockDim.x + threadIdx.x;
    if (i < n) p[i] = 0;
}

__global__ void k_count(const int* __restrict__ dst, int* __restrict__ cnt, int e) {
    int i = blockIdx.x * blockDim.x + threadIdx.x;
    if (i < e) atomicAdd(&cnt[dst[i]], 1);
}

// pass 1: per-block (1024 elements) sums
__global__ void k_bsum(const int* __restrict__ cnt, int* __restrict__ part, int n) {
    __shared__ int sm[8];
    int b = blockIdx.x, t = threadIdx.x;
    int base = b * 1024 + t * 4;
    int s = 0;
    if (base + 3 < n) {
        int4 v = *(const int4*)(cnt + base);
        s = v.x + v.y + v.z + v.w;
    } else {
        for (int i = 0; i < 4; i++) if (base + i < n) s += cnt[base + i];
    }
    for (int o = 16; o; o >>= 1) s += __shfl_down_sync(0xffffffffu, s, o);
    if ((t & 31) == 0) sm[t >> 5] = s;
    __syncthreads();
    if (t < 8) {
        int v = sm[t];
        for (int o = 4; o; o >>= 1) v += __shfl_down_sync(0xffu, v, o);
        if (t == 0) part[b] = v;
    }
}

// pass 2: exclusive scan of block partials (nb <= 128)
__global__ void k_pscan(int* __restrict__ part, int nb) {
    __shared__ int sm[128];
    int t = threadIdx.x;
    int v = (t < nb) ? part[t] : 0;
    sm[t] = v;
    __syncthreads();
    for (int o = 1; o < 128; o <<= 1) {
        int u = (t >= o) ? sm[t - o] : 0;
        __syncthreads();
        sm[t] += u;
        __syncthreads();
    }
    if (t < nb) part[t] = sm[t] - v;
}

// pass 3: write rowptr/cursor/dinv
__global__ void k_wptr(const int* __restrict__ cnt, const int* __restrict__ part,
                       int* __restrict__ rowptr, int* __restrict__ cursor,
                       float* __restrict__ dinv, int n) {
    __shared__ int sm[256];
    int b = blockIdx.x, t = threadIdx.x;
    int base = b * 1024 + t * 4;
    int c[4];
#pragma unroll
    for (int i = 0; i < 4; i++) c[i] = (base + i < n) ? cnt[base + i] : 0;
    int tsum = c[0] + c[1] + c[2] + c[3];
    sm[t] = tsum;
    __syncthreads();
    for (int o = 1; o < 256; o <<= 1) {
        int u = (t >= o) ? sm[t - o] : 0;
        __syncthreads();
        sm[t] += u;
        __syncthreads();
    }
    int run = part[b] + sm[t] - tsum;
#pragma unroll
    for (int i = 0; i < 4; i++) {
        int idx = base + i;
        if (idx < n) {
            rowptr[idx] = run;
            cursor[idx] = run;
            dinv[idx] = rsqrtf((float)(c[i] + 1));
            if (idx == n - 1) rowptr[n] = run + c[i];
            run += c[i];
        }
    }
}

__global__ void k_fill(const int* __restrict__ src, const int* __restrict__ dst,
                       int* __restrict__ cursor, int* __restrict__ col, int e) {
    int i = blockIdx.x * blockDim.x + threadIdx.x;
    if (i < e) {
        int p = atomicAdd(&cursor[dst[i]], 1);
        col[p] = src[i];
    }
}

// ---------------- packed dual-fp32 helpers ----------------
__device__ __forceinline__ void fma2(unsigned long long& d,
                                     unsigned long long a, unsigned long long b) {
    asm("fma.rn.f32x2 %0, %1, %2, %0;" : "+l"(d) : "l"(a), "l"(b));
}
__device__ __forceinline__ unsigned long long dup2(float x) {
    unsigned long long r;
    asm("mov.b64 %0, {%1, %1};" : "=l"(r) : "f"(x));
    return r;
}
__device__ __forceinline__ float2 unpack2(unsigned long long v) {
    float2 r;
    asm("mov.b64 {%0, %1}, %2;" : "=f"(r.x), "=f"(r.y) : "l"(v));
    return r;
}

// ---------------- GEMM:  T[r][c] = dinv[r] * sum_k X[r][k] * W[k][c] ----------------
// block tile: 128 rows x OUT cols, 128 threads.
// thread tile: 8 rows x (OUT/8) f32x2 column pairs.
// A stored scalar (stride 33, conflict-free), packed to f32x2 in registers.
template <int OUT>
__global__ void __launch_bounds__(128)
k_gemm(const float* __restrict__ X, const float* __restrict__ W,
       const float* __restrict__ dinv, float* __restrict__ T, int n) {
    constexpr int KC = 32;
    constexpr int LDA = KC + 1;          // 33: pad to kill LDS bank conflicts
    constexpr int NJ = OUT / 16;         // f32x2 pairs per thread
    __shared__ float As[128 * LDA];      // ~16.5 KB
    __shared__ __align__(16) float Ws[KC * OUT];  // 16 KB (OUT=128) / 8 KB

    int tid = threadIdx.x;
    int tx = tid & 7;    // 8 column groups
    int ty = tid >> 3;   // 16 row groups (8 rows each)
    int rb = blockIdx.x * 128;

    unsigned long long acc[8][NJ];
#pragma unroll
    for (int i = 0; i < 8; i++)
#pragma unroll
        for (int j = 0; j < NJ; j++) acc[i][j] = 0ull;

    for (int kc = 0; kc < 128; kc += KC) {
        // load A tile (128 x 32) scalar
        {
            int c4 = tid & 7;      // 8 float4 per row
            int r0 = tid >> 3;     // 16 rows per pass
#pragma unroll
            for (int p = 0; p < 8; p++) {
                int row = r0 + p * 16;
                int g = rb + row;
                float4 v = make_float4(0.f, 0.f, 0.f, 0.f);
                if (g < n) v = *(const float4*)(X + (size_t)g * 128 + kc + c4 * 4);
                float* d = As + row * LDA + c4 * 4;
                d[0] = v.x; d[1] = v.y; d[2] = v.z; d[3] = v.w;
            }
        }
        // load W tile (KC x OUT), contiguous
        {
            constexpr int NF4 = KC * OUT / 4;
#pragma unroll
            for (int i = tid; i < NF4; i += 128)
                *(float4*)(Ws + (size_t)i * 4) = *(const float4*)(W + (size_t)kc * OUT + (size_t)i * 4);
        }
        __syncthreads();

#pragma unroll 4
        for (int k = 0; k < KC; k++) {
            unsigned long long a2[8], w[NJ];
#pragma unroll
            for (int i = 0; i < 8; i++)
                a2[i] = dup2(As[(ty * 8 + i) * LDA + k]);
#pragma unroll
            for (int j = 0; j < NJ; j++)
                w[j] = *(const unsigned long long*)(Ws + k * OUT + 2 * tx + 16 * j);
#pragma unroll
            for (int i = 0; i < 8; i++)
#pragma unroll
                for (int j = 0; j < NJ; j++)
                    fma2(acc[i][j], a2[i], w[j]);
        }
        __syncthreads();
    }

#pragma unroll
    for (int i = 0; i < 8; i++) {
        int row = rb + ty * 8 + i;
        if (row < n) {
            float sc = dinv[row];
#pragma unroll
            for (int j = 0; j < NJ; j++) {
                float2 v = unpack2(acc[i][j]);
                v.x *= sc; v.y *= sc;
                *(float2*)(T + (size_t)row * OUT + 2 * tx + 16 * j) = v;
            }
        }
    }
}

// ---------------- aggregation:  Y[d] = act( dinv[d]*(T[d] + sum_{s in N(d)} T[s]) + b ) ----
// one warp per destination node; lane owns C/32 contiguous columns.
template <int C, bool RELU>
__global__ void __launch_bounds__(256)
k_agg(const float* __restrict__ T, const float* __restrict__ bias,
      const float* __restrict__ dinv, const int* __restrict__ rowptr,
      const int* __restrict__ col, float* __restrict__ Y, int n) {
    constexpr int V = C / 32;   // 4 or 2
    int w = (int)((blockIdx.x * 256 + threadIdx.x) >> 5);
    if (w >= n) return;
    int lane = threadIdx.x & 31;

    float acc[V];
    {
        const float* p = T + (size_t)w * C + lane * V;
        if (V == 4) {
            float4 t = *(const float4*)p;
            acc[0] = t.x; acc[1] = t.y; acc[2] = t.z; acc[3] = t.w;
        } else {
            float2 t = *(const float2*)p;
            acc[0] = t.x; acc[1] = t.y;
        }
    }

    int e = rowptr[w];
    int e1 = rowptr[w + 1];
    while (e < e1) {
        int m = min(32, e1 - e);
        int sidx = (lane < m) ? col[e + lane] : 0;
#pragma unroll 4
        for (int j = 0; j < m; j++) {
            int s = __shfl_sync(0xffffffffu, sidx, j);
            const float* p = T + (size_t)s * C + lane * V;
            if (V == 4) {
                float4 t = *(const float4*)p;
                acc[0] += t.x; acc[1] += t.y; acc[2] += t.z; acc[3] += t.w;
            } else {
                float2 t = *(const float2*)p;
                acc[0] += t.x; acc[1] += t.y;
            }
        }
        e += m;
    }

    float sc = dinv[w];
    float o[V];
    {
        const float* bp = bias + lane * V;
        if (V == 4) {
            float4 b = *(const float4*)bp;
            o[0] = fmaf(acc[0], sc, b.x);
            o[1] = fmaf(acc[1], sc, b.y);
            o[2] = fmaf(acc[2], sc, b.z);
            o[3] = fmaf(acc[3], sc, b.w);
        } else {
            float2 b = *(const float2*)bp;
            o[0] = fmaf(acc[0], sc, b.x);
            o[1] = fmaf(acc[1], sc, b.y);
        }
    }
    if (RELU) {
#pragma unroll
        for (int v = 0; v < V; v++) o[v] = fmaxf(o[v], 0.0f);
    }
    {
        float* p = Y + (size_t)w * C + lane * V;
        if (V == 4) *(float4*)p = make_float4(o[0], o[1], o[2], o[3]);
        else        *(float2*)p = make_float2(o[0], o[1]);
    }
}

// ---------------- launcher ----------------
extern "C" void kernel_launch(void* const* d_in, const int* in_sizes, int n_in,
                              void* d_out, int out_size) {
    const float* x  = (const float*)d_in[0];
    const int*   ei = (const int*)d_in[1];
    const float* W0 = (const float*)d_in[2];
    const float* b0 = (const float*)d_in[3];
    const float* W1 = (const float*)d_in[4];
    const float* b1 = (const float*)d_in[5];
    const float* W2 = (const float*)d_in[6];
    const float* b2 = (const float*)d_in[7];
    const float* W3 = (const float*)d_in[8];
    const float* b3 = (const float*)d_in[9];

    int N = in_sizes[0] / 128;
    int E = in_sizes[1] / 2;
    const int* src = ei;
    const int* dst = ei + E;

    float *T, *Y, *dinv;
    int *cnt, *rowptr, *cursor, *colx, *part;
    cudaGetSymbolAddress((void**)&T, g_T);
    cudaGetSymbolAddress((void**)&Y, g_Y);
    cudaGetSymbolAddress((void**)&dinv, g_dinv);
    cudaGetSymbolAddress((void**)&cnt, g_cnt);
    cudaGetSymbolAddress((void**)&rowptr, g_rowptr);
    cudaGetSymbolAddress((void**)&cursor, g_cursor);
    cudaGetSymbolAddress((void**)&colx, g_col);
    cudaGetSymbolAddress((void**)&part, g_part);

    int nb = (N + 1023) / 1024;   // scan blocks (<=128)

    // CSR build (per call; graph-capturable, deterministic work)
    k_zero <<<(N + 255) / 256, 256>>>(cnt, N);
    k_count<<<(E + 255) / 256, 256>>>(dst, cnt, E);
    k_bsum <<<nb, 256>>>(cnt, part, N);
    k_pscan<<<1, 128>>>(part, nb);
    k_wptr <<<nb, 256>>>(cnt, part, rowptr, cursor, dinv, N);
    k_fill <<<(E + 255) / 256, 256>>>(src, dst, cursor, colx, E);

    int gg = (N + 127) / 128;
    int ga = (N + 7) / 8;

    // layer 0: GCNConv(D=128 -> H=128) + ReLU
    k_gemm<128><<<gg, 128>>>(x, W0, dinv, T, N);
    k_agg<128, true><<<ga, 256>>>(T, b0, dinv, rowptr, colx, Y, N);
    // layer 1
    k_gemm<128><<<gg, 128>>>(Y, W1, dinv, T, N);
    k_agg<128, true><<<ga, 256>>>(T, b1, dinv, rowptr, colx, Y, N);
    // layer 2
    k_gemm<128><<<gg, 128>>>(Y, W2, dinv, T, N);
    k_agg<128, true><<<ga, 256>>>(T, b2, dinv, rowptr, colx, Y, N);
    // layer 3: GCNConv(H=128 -> O=64), no activation, write d_out
    k_gemm<64><<<gg, 128>>>(Y, W3, dinv, T, N);
    k_agg<64, false><<<ga, 256>>>(T, b3, dinv, rowptr, colx, (float*)d_out, N);
}

// round 4
// speedup vs baseline: 1.7676x; 1.1785x over previous
#include <cuda_runtime.h>
#include <cuda_bf16.h>
#include <cstdint>
#include <cstddef>

#define MAXN 100000
#define MAXE 1600000

// ---------------- device scratch (static, no allocation) ----------------
__device__ float g_T[(size_t)MAXN * 128];   // GEMM output, pre-scaled by dinv[row]
__device__ float g_Y[(size_t)MAXN * 128];   // layer output / next layer input
__device__ float g_dinv[MAXN];
__device__ int   g_cnt[MAXN];
__device__ int   g_rowptr[MAXN + 1];
__device__ int   g_cursor[MAXN];
__device__ int   g_col[MAXE];
__device__ int   g_part[256];
__device__ __nv_bfloat16 g_whi[128 * 128];  // W^T split, [n][k] row-major
__device__ __nv_bfloat16 g_wlo[128 * 128];

// ---------------- CSR build ----------------
__global__ void k_zero(int* __restrict__ p, int n) {
    int i = blockIdx.x * blockDim.x + threadIdx.x;
    if (i < n) p[i] = 0;
}
__global__ void k_count(const int* __restrict__ dst, int* __restrict__ cnt, int e) {
    int i = blockIdx.x * blockDim.x + threadIdx.x;
    if (i < e) atomicAdd(&cnt[dst[i]], 1);
}
__global__ void k_bsum(const int* __restrict__ cnt, int* __restrict__ part, int n) {
    __shared__ int sm[8];
    int b = blockIdx.x, t = threadIdx.x;
    int base = b * 1024 + t * 4;
    int s = 0;
    if (base + 3 < n) {
        int4 v = *(const int4*)(cnt + base);
        s = v.x + v.y + v.z + v.w;
    } else {
        for (int i = 0; i < 4; i++) if (base + i < n) s += cnt[base + i];
    }
    for (int o = 16; o; o >>= 1) s += __shfl_down_sync(0xffffffffu, s, o);
    if ((t & 31) == 0) sm[t >> 5] = s;
    __syncthreads();
    if (t < 8) {
        int v = sm[t];
        for (int o = 4; o; o >>= 1) v += __shfl_down_sync(0xffu, v, o);
        if (t == 0) part[b] = v;
    }
}
__global__ void k_pscan(int* __restrict__ part, int nb) {
    __shared__ int sm[128];
    int t = threadIdx.x;
    int v = (t < nb) ? part[t] : 0;
    sm[t] = v;
    __syncthreads();
    for (int o = 1; o < 128; o <<= 1) {
        int u = (t >= o) ? sm[t - o] : 0;
        __syncthreads();
        sm[t] += u;
        __syncthreads();
    }
    if (t < nb) part[t] = sm[t] - v;
}
__global__ void k_wptr(const int* __restrict__ cnt, const int* __restrict__ part,
                       int* __restrict__ rowptr, int* __restrict__ cursor,
                       float* __restrict__ dinv, int n) {
    __shared__ int sm[256];
    int b = blockIdx.x, t = threadIdx.x;
    int base = b * 1024 + t * 4;
    int c[4];
#pragma unroll
    for (int i = 0; i < 4; i++) c[i] = (base + i < n) ? cnt[base + i] : 0;
    int tsum = c[0] + c[1] + c[2] + c[3];
    sm[t] = tsum;
    __syncthreads();
    for (int o = 1; o < 256; o <<= 1) {
        int u = (t >= o) ? sm[t - o] : 0;
        __syncthreads();
        sm[t] += u;
        __syncthreads();
    }
    int run = part[b] + sm[t] - tsum;
#pragma unroll
    for (int i = 0; i < 4; i++) {
        int idx = base + i;
        if (idx < n) {
            rowptr[idx] = run;
            cursor[idx] = run;
            dinv[idx] = rsqrtf((float)(c[i] + 1));
            if (idx == n - 1) rowptr[n] = run + c[i];
            run += c[i];
        }
    }
}
__global__ void k_fill(const int* __restrict__ src, const int* __restrict__ dst,
                       int* __restrict__ cursor, int* __restrict__ col, int e) {
    int i = blockIdx.x * blockDim.x + threadIdx.x;
    if (i < e) {
        int p = atomicAdd(&cursor[dst[i]], 1);
        col[p] = src[i];
    }
}

// ---------------- W transpose + bf16 split:  B[n][k] = W[k][n] ----------------
__global__ void k_wconv(const float* __restrict__ W, __nv_bfloat16* __restrict__ bhi,
                        __nv_bfloat16* __restrict__ blo, int outn) {
    int i = blockIdx.x * blockDim.x + threadIdx.x;
    if (i < 128 * outn) {
        int k = i / outn, nn = i - k * outn;
        float w = W[i];
        __nv_bfloat16 h = __float2bfloat16(w);
        float r = w - __bfloat162float(h);
        bhi[nn * 128 + k] = h;
        blo[nn * 128 + k] = __float2bfloat16(r);
    }
}

// ---------------- mma.sync helpers ----------------
__device__ __forceinline__ uint32_t smem_u32(const void* p) {
    uint32_t a;
    asm("{ .reg .u64 t; cvta.to.shared.u64 t, %1; cvt.u32.u64 %0, t; }" : "=r"(a) : "l"(p));
    return a;
}
__device__ __forceinline__ void ldmat_x4(uint32_t* r, uint32_t addr) {
    asm volatile("ldmatrix.sync.aligned.m8n8.x4.shared.b16 {%0,%1,%2,%3}, [%4];"
                 : "=r"(r[0]), "=r"(r[1]), "=r"(r[2]), "=r"(r[3]) : "r"(addr));
}
__device__ __forceinline__ void mma16816(float* c, const uint32_t* a, const uint32_t* b) {
    asm volatile("mma.sync.aligned.m16n8k16.row.col.f32.bf16.bf16.f32 "
                 "{%0,%1,%2,%3}, {%4,%5,%6,%7}, {%8,%9}, {%0,%1,%2,%3};"
                 : "+f"(c[0]), "+f"(c[1]), "+f"(c[2]), "+f"(c[3])
                 : "r"(a[0]), "r"(a[1]), "r"(a[2]), "r"(a[3]), "r"(b[0]), "r"(b[1]));
}

// ---------------- tensor GEMM:  T[r][c] = dinv[r] * sum_k X[r][k] * W[k][c] --------
// CTA: 128 rows x OUT cols, 256 threads (8 warps).
// bf16 2-way split (hi*hi + hi*lo + lo*hi). A in SMEM (272B stride, ldmatrix-friendly),
// B fragments read directly from GMEM (W^T is 32KB, L1-resident, shared by all CTAs).
template <int OUT>
__global__ void __launch_bounds__(256)
k_gemm_mma(const float* __restrict__ X, const __nv_bfloat16* __restrict__ Bhi,
           const __nv_bfloat16* __restrict__ Blo, const float* __restrict__ dinv,
           float* __restrict__ T, int n) {
    constexpr int NWN = OUT / 32;      // warps along n: 4 (OUT=128) or 2 (OUT=64)
    constexpr int NWM = 8 / NWN;       // warps along m: 2 or 4
    constexpr int WM  = 128 / NWM;     // rows per warp: 64 or 32
    constexpr int MT  = WM / 16;       // m16 tiles per warp: 4 or 2
    constexpr int NT  = 4;             // n8 tiles per warp (32 cols)
    constexpr int LDA = 272;           // bytes per A row: odd multiple of 16B

    extern __shared__ __align__(16) char smem[];
    char* a_hi = smem;
    char* a_lo = smem + 128 * LDA;
    uint32_t sb_hi = smem_u32(a_hi);
    uint32_t sb_lo = smem_u32(a_lo);

    int tid = threadIdx.x;
    int lane = tid & 31, wid = tid >> 5;
    int wm = wid % NWM, wn = wid / NWM;
    int mbase = wm * WM, nbase = wn * 32;
    int rb = blockIdx.x * 128;

    // ---- load X tile (128 x 128 fp32), split to bf16 hi/lo in SMEM ----
#pragma unroll
    for (int it = 0; it < 16; it++) {
        int i = tid + it * 256;          // 4096 float4 slots
        int row = i >> 5, f4 = i & 31;
        int g = rb + row;
        float4 v = make_float4(0.f, 0.f, 0.f, 0.f);
        if (g < n) v = *(const float4*)(X + (size_t)g * 128 + f4 * 4);

        __nv_bfloat16 hx = __float2bfloat16(v.x), hy = __float2bfloat16(v.y);
        __nv_bfloat16 hz = __float2bfloat16(v.z), hw = __float2bfloat16(v.w);
        __nv_bfloat16 lx = __float2bfloat16(v.x - __bfloat162float(hx));
        __nv_bfloat16 ly = __float2bfloat16(v.y - __bfloat162float(hy));
        __nv_bfloat16 lz = __float2bfloat16(v.z - __bfloat162float(hz));
        __nv_bfloat16 lw = __float2bfloat16(v.w - __bfloat162float(hw));

        uint2 hp, lp;
        hp.x = ((uint32_t)__bfloat16_as_ushort(hy) << 16) | __bfloat16_as_ushort(hx);
        hp.y = ((uint32_t)__bfloat16_as_ushort(hw) << 16) | __bfloat16_as_ushort(hz);
        lp.x = ((uint32_t)__bfloat16_as_ushort(ly) << 16) | __bfloat16_as_ushort(lx);
        lp.y = ((uint32_t)__bfloat16_as_ushort(lw) << 16) | __bfloat16_as_ushort(lz);
        int off = row * LDA + f4 * 8;
        *(uint2*)(a_hi + off) = hp;
        *(uint2*)(a_lo + off) = lp;
    }
    __syncthreads();

    float acc[MT][NT][4];
#pragma unroll
    for (int i = 0; i < MT; i++)
#pragma unroll
        for (int j = 0; j < NT; j++)
#pragma unroll
            for (int q = 0; q < 4; q++) acc[i][j][q] = 0.f;

    // ldmatrix per-lane address pieces (constant across k-steps except k offset)
    int lrow = (lane & 7) + ((lane >> 3) & 1) * 8;   // row within 16-row tile
    int lkh  = lane >> 4;                             // k-half (0/1)

#pragma unroll
    for (int ks = 0; ks < 8; ks++) {
        int kb = ks * 16;
        uint32_t ah[MT][4], al[MT][4];
#pragma unroll
        for (int mt = 0; mt < MT; mt++) {
            uint32_t off = (uint32_t)((mbase + mt * 16 + lrow) * LDA + (kb + lkh * 8) * 2);
            ldmat_x4(ah[mt], sb_hi + off);
            ldmat_x4(al[mt], sb_lo + off);
        }
        uint32_t bh[NT][2], bl[NT][2];
#pragma unroll
        for (int j = 0; j < NT; j++) {
            int nn = nbase + j * 8 + (lane >> 2);
            int k0 = kb + (lane & 3) * 2;
            const __nv_bfloat16* ph = Bhi + (size_t)nn * 128 + k0;
            const __nv_bfloat16* pl = Blo + (size_t)nn * 128 + k0;
            bh[j][0] = *(const uint32_t*)ph;
            bh[j][1] = *(const uint32_t*)(ph + 8);
            bl[j][0] = *(const uint32_t*)pl;
            bl[j][1] = *(const uint32_t*)(pl + 8);
        }
#pragma unroll
        for (int mt = 0; mt < MT; mt++)
#pragma unroll
            for (int j = 0; j < NT; j++) {
                mma16816(acc[mt][j], ah[mt], bh[j]);
                mma16816(acc[mt][j], ah[mt], bl[j]);
                mma16816(acc[mt][j], al[mt], bh[j]);
            }
    }

    // ---- epilogue: scale by dinv[row], store ----
#pragma unroll
    for (int mt = 0; mt < MT; mt++) {
        int r0 = rb + mbase + mt * 16 + (lane >> 2);
        int r1 = r0 + 8;
        float s0 = (r0 < n) ? dinv[r0] : 0.f;
        float s1 = (r1 < n) ? dinv[r1] : 0.f;
#pragma unroll
        for (int j = 0; j < NT; j++) {
            int col = nbase + j * 8 + (lane & 3) * 2;
            if (r0 < n)
                *(float2*)(T + (size_t)r0 * OUT + col) =
                    make_float2(acc[mt][j][0] * s0, acc[mt][j][1] * s0);
            if (r1 < n)
                *(float2*)(T + (size_t)r1 * OUT + col) =
                    make_float2(acc[mt][j][2] * s1, acc[mt][j][3] * s1);
        }
    }
}

// ---------------- aggregation:  Y[d] = act( dinv[d]*(T[d] + sum_{s} T[s]) + b ) ------
template <int C, bool RELU>
__global__ void __launch_bounds__(256)
k_agg(const float* __restrict__ T, const float* __restrict__ bias,
      const float* __restrict__ dinv, const int* __restrict__ rowptr,
      const int* __restrict__ col, float* __restrict__ Y, int n) {
    constexpr int V = C / 32;
    int w = (int)((blockIdx.x * 256 + threadIdx.x) >> 5);
    if (w >= n) return;
    int lane = threadIdx.x & 31;

    float acc[V];
    {
        const float* p = T + (size_t)w * C + lane * V;
        if (V == 4) {
            float4 t = *(const float4*)p;
            acc[0] = t.x; acc[1] = t.y; acc[2] = t.z; acc[3] = t.w;
        } else {
            float2 t = *(const float2*)p;
            acc[0] = t.x; acc[1] = t.y;
        }
    }

    int e = rowptr[w];
    int e1 = rowptr[w + 1];
    while (e < e1) {
        int m = min(32, e1 - e);
        int sidx = (lane < m) ? col[e + lane] : 0;
#pragma unroll 4
        for (int j = 0; j < m; j++) {
            int s = __shfl_sync(0xffffffffu, sidx, j);
            const float* p = T + (size_t)s * C + lane * V;
            if (V == 4) {
                float4 t = *(const float4*)p;
                acc[0] += t.x; acc[1] += t.y; acc[2] += t.z; acc[3] += t.w;
            } else {
                float2 t = *(const float2*)p;
                acc[0] += t.x; acc[1] += t.y;
            }
        }
        e += m;
    }

    float sc = dinv[w];
    float o[V];
    {
        const float* bp = bias + lane * V;
        if (V == 4) {
            float4 b = *(const float4*)bp;
            o[0] = fmaf(acc[0], sc, b.x);
            o[1] = fmaf(acc[1], sc, b.y);
            o[2] = fmaf(acc[2], sc, b.z);
            o[3] = fmaf(acc[3], sc, b.w);
        } else {
            float2 b = *(const float2*)bp;
            o[0] = fmaf(acc[0], sc, b.x);
            o[1] = fmaf(acc[1], sc, b.y);
        }
    }
    if (RELU) {
#pragma unroll
        for (int v = 0; v < V; v++) o[v] = fmaxf(o[v], 0.0f);
    }
    {
        float* p = Y + (size_t)w * C + lane * V;
        if (V == 4) *(float4*)p = make_float4(o[0], o[1], o[2], o[3]);
        else        *(float2*)p = make_float2(o[0], o[1]);
    }
}

// ---------------- launcher ----------------
extern "C" void kernel_launch(void* const* d_in, const int* in_sizes, int n_in,
                              void* d_out, int out_size) {
    const float* x  = (const float*)d_in[0];
    const int*   ei = (const int*)d_in[1];
    const float* W0 = (const float*)d_in[2];
    const float* b0 = (const float*)d_in[3];
    const float* W1 = (const float*)d_in[4];
    const float* b1 = (const float*)d_in[5];
    const float* W2 = (const float*)d_in[6];
    const float* b2 = (const float*)d_in[7];
    const float* W3 = (const float*)d_in[8];
    const float* b3 = (const float*)d_in[9];

    int N = in_sizes[0] / 128;
    int E = in_sizes[1] / 2;
    const int* src = ei;
    const int* dst = ei + E;

    float *T, *Y, *dinv;
    int *cnt, *rowptr, *cursor, *colx, *part;
    __nv_bfloat16 *whi, *wlo;
    cudaGetSymbolAddress((void**)&T, g_T);
    cudaGetSymbolAddress((void**)&Y, g_Y);
    cudaGetSymbolAddress((void**)&dinv, g_dinv);
    cudaGetSymbolAddress((void**)&cnt, g_cnt);
    cudaGetSymbolAddress((void**)&rowptr, g_rowptr);
    cudaGetSymbolAddress((void**)&cursor, g_cursor);
    cudaGetSymbolAddress((void**)&colx, g_col);
    cudaGetSymbolAddress((void**)&part, g_part);
    cudaGetSymbolAddress((void**)&whi, g_whi);
    cudaGetSymbolAddress((void**)&wlo, g_wlo);

    constexpr int SMEM_A = 2 * 128 * 272;   // 69632 bytes
    cudaFuncSetAttribute(k_gemm_mma<128>, cudaFuncAttributeMaxDynamicSharedMemorySize, SMEM_A);
    cudaFuncSetAttribute(k_gemm_mma<64>,  cudaFuncAttributeMaxDynamicSharedMemorySize, SMEM_A);

    int nb = (N + 1023) / 1024;

    // CSR build
    k_zero <<<(N + 255) / 256, 256>>>(cnt, N);
    k_count<<<(E + 255) / 256, 256>>>(dst, cnt, E);
    k_bsum <<<nb, 256>>>(cnt, part, N);
    k_pscan<<<1, 128>>>(part, nb);
    k_wptr <<<nb, 256>>>(cnt, part, rowptr, cursor, dinv, N);
    k_fill <<<(E + 255) / 256, 256>>>(src, dst, cursor, colx, E);

    int gg = (N + 127) / 128;
    int ga = (N + 7) / 8;

    // layer 0
    k_wconv<<<(128 * 128 + 255) / 256, 256>>>(W0, whi, wlo, 128);
    k_gemm_mma<128><<<gg, 256, SMEM_A>>>(x, whi, wlo, dinv, T, N);
    k_agg<128, true><<<ga, 256>>>(T, b0, dinv, rowptr, colx, Y, N);
    // layer 1
    k_wconv<<<(128 * 128 + 255) / 256, 256>>>(W1, whi, wlo, 128);
    k_gemm_mma<128><<<gg, 256, SMEM_A>>>(Y, whi, wlo, dinv, T, N);
    k_agg<128, true><<<ga, 256>>>(T, b1, dinv, rowptr, colx, Y, N);
    // layer 2
    k_wconv<<<(128 * 128 + 255) / 256, 256>>>(W2, whi, wlo, 128);
    k_gemm_mma<128><<<gg, 256, SMEM_A>>>(Y, whi, wlo, dinv, T, N);
    k_agg<128, true><<<ga, 256>>>(T, b2, dinv, rowptr, colx, Y, N);
    // layer 3: H=128 -> O=64, no activation
    k_wconv<<<(128 * 64 + 255) / 256, 256>>>(W3, whi, wlo, 64);
    k_gemm_mma<64><<<gg, 256, SMEM_A>>>(Y, whi, wlo, dinv, T, N);
    k_agg<64, false><<<ga, 256>>>(T, b3, dinv, rowptr, colx, (float*)d_out, N);
}

// round 5
// speedup vs baseline: 1.8730x; 1.0597x over previous
#include <cuda_runtime.h>
#include <cuda_bf16.h>
#include <cuda_fp16.h>
#include <cstdint>
#include <cstddef>

#define MAXN 100000
#define MAXE 1600000

// ---------------- device scratch (static, no allocation) ----------------
__device__ __half g_Th[(size_t)MAXN * 128]; // GEMM output (pre-scaled by dinv), fp16
__device__ float g_Y[(size_t)MAXN * 128];   // layer output / next layer input
__device__ float g_dinv[MAXN];
__device__ int   g_cnt[MAXN];
__device__ int   g_rowptr[MAXN + 1];
__device__ int   g_cursor[MAXN];
__device__ int   g_col[MAXE];
__device__ int   g_part[256];
__device__ __nv_bfloat16 g_whi[128 * 128];  // W^T split, [n][k] row-major
__device__ __nv_bfloat16 g_wlo[128 * 128];

// ---------------- CSR build ----------------
__global__ void k_zero(int* __restrict__ p, int n) {
    int i = blockIdx.x * blockDim.x + threadIdx.x;
    if (i < n) p[i] = 0;
}
__global__ void k_count(const int* __restrict__ dst, int* __restrict__ cnt, int e) {
    int i = blockIdx.x * blockDim.x + threadIdx.x;
    if (i < e) atomicAdd(&cnt[dst[i]], 1);
}
__global__ void k_bsum(const int* __restrict__ cnt, int* __restrict__ part, int n) {
    __shared__ int sm[8];
    int b = blockIdx.x, t = threadIdx.x;
    int base = b * 1024 + t * 4;
    int s = 0;
    if (base + 3 < n) {
        int4 v = *(const int4*)(cnt + base);
        s = v.x + v.y + v.z + v.w;
    } else {
        for (int i = 0; i < 4; i++) if (base + i < n) s += cnt[base + i];
    }
    for (int o = 16; o; o >>= 1) s += __shfl_down_sync(0xffffffffu, s, o);
    if ((t & 31) == 0) sm[t >> 5] = s;
    __syncthreads();
    if (t < 8) {
        int v = sm[t];
        for (int o = 4; o; o >>= 1) v += __shfl_down_sync(0xffu, v, o);
        if (t == 0) part[b] = v;
    }
}
__global__ void k_pscan(int* __restrict__ part, int nb) {
    __shared__ int sm[128];
    int t = threadIdx.x;
    int v = (t < nb) ? part[t] : 0;
    sm[t] = v;
    __syncthreads();
    for (int o = 1; o < 128; o <<= 1) {
        int u = (t >= o) ? sm[t - o] : 0;
        __syncthreads();
        sm[t] += u;
        __syncthreads();
    }
    if (t < nb) part[t] = sm[t] - v;
}
__global__ void k_wptr(const int* __restrict__ cnt, const int* __restrict__ part,
                       int* __restrict__ rowptr, int* __restrict__ cursor,
                       float* __restrict__ dinv, int n) {
    __shared__ int sm[256];
    int b = blockIdx.x, t = threadIdx.x;
    int base = b * 1024 + t * 4;
    int c[4];
#pragma unroll
    for (int i = 0; i < 4; i++) c[i] = (base + i < n) ? cnt[base + i] : 0;
    int tsum = c[0] + c[1] + c[2] + c[3];
    sm[t] = tsum;
    __syncthreads();
    for (int o = 1; o < 256; o <<= 1) {
        int u = (t >= o) ? sm[t - o] : 0;
        __syncthreads();
        sm[t] += u;
        __syncthreads();
    }
    int run = part[b] + sm[t] - tsum;
#pragma unroll
    for (int i = 0; i < 4; i++) {
        int idx = base + i;
        if (idx < n) {
            rowptr[idx] = run;
            cursor[idx] = run;
            dinv[idx] = rsqrtf((float)(c[i] + 1));
            if (idx == n - 1) rowptr[n] = run + c[i];
            run += c[i];
        }
    }
}
__global__ void k_fill(const int* __restrict__ src, const int* __restrict__ dst,
                       int* __restrict__ cursor, int* __restrict__ col, int e) {
    int i = blockIdx.x * blockDim.x + threadIdx.x;
    if (i < e) {
        int p = atomicAdd(&cursor[dst[i]], 1);
        col[p] = src[i];
    }
}

// ---------------- W transpose + bf16 split:  B[n][k] = W[k][n] ----------------
__global__ void k_wconv(const float* __restrict__ W, __nv_bfloat16* __restrict__ bhi,
                        __nv_bfloat16* __restrict__ blo, int outn) {
    int i = blockIdx.x * blockDim.x + threadIdx.x;
    if (i < 128 * outn) {
        int k = i / outn, nn = i - k * outn;
        float w = W[i];
        __nv_bfloat16 h = __float2bfloat16(w);
        float r = w - __bfloat162float(h);
        bhi[nn * 128 + k] = h;
        blo[nn * 128 + k] = __float2bfloat16(r);
    }
}

// ---------------- mma.sync helpers ----------------
__device__ __forceinline__ uint32_t smem_u32(const void* p) {
    uint32_t a;
    asm("{ .reg .u64 t; cvta.to.shared.u64 t, %1; cvt.u32.u64 %0, t; }" : "=r"(a) : "l"(p));
    return a;
}
__device__ __forceinline__ void ldmat_x4(uint32_t* r, uint32_t addr) {
    asm volatile("ldmatrix.sync.aligned.m8n8.x4.shared.b16 {%0,%1,%2,%3}, [%4];"
                 : "=r"(r[0]), "=r"(r[1]), "=r"(r[2]), "=r"(r[3]) : "r"(addr));
}
__device__ __forceinline__ void mma16816(float* c, const uint32_t* a, const uint32_t* b) {
    asm volatile("mma.sync.aligned.m16n8k16.row.col.f32.bf16.bf16.f32 "
                 "{%0,%1,%2,%3}, {%4,%5,%6,%7}, {%8,%9}, {%0,%1,%2,%3};"
                 : "+f"(c[0]), "+f"(c[1]), "+f"(c[2]), "+f"(c[3])
                 : "r"(a[0]), "r"(a[1]), "r"(a[2]), "r"(a[3]), "r"(b[0]), "r"(b[1]));
}

// ---------------- tensor GEMM:  Th[r][c] = fp16( dinv[r] * sum_k X[r][k] * W[k][c] ) --
// CTA: 128 rows x OUT cols, 256 threads (8 warps). bf16 2-way split MMA.
template <int OUT>
__global__ void __launch_bounds__(256)
k_gemm_mma(const float* __restrict__ X, const __nv_bfloat16* __restrict__ Bhi,
           const __nv_bfloat16* __restrict__ Blo, const float* __restrict__ dinv,
           __half* __restrict__ T, int n) {
    constexpr int NWN = OUT / 32;
    constexpr int NWM = 8 / NWN;
    constexpr int WM  = 128 / NWM;
    constexpr int MT  = WM / 16;
    constexpr int NT  = 4;
    constexpr int LDA = 272;

    extern __shared__ __align__(16) char smem[];
    char* a_hi = smem;
    char* a_lo = smem + 128 * LDA;
    uint32_t sb_hi = smem_u32(a_hi);
    uint32_t sb_lo = smem_u32(a_lo);

    int tid = threadIdx.x;
    int lane = tid & 31, wid = tid >> 5;
    int wm = wid % NWM, wn = wid / NWM;
    int mbase = wm * WM, nbase = wn * 32;
    int rb = blockIdx.x * 128;

    // ---- load X tile (128 x 128 fp32), split to bf16 hi/lo in SMEM ----
#pragma unroll
    for (int it = 0; it < 16; it++) {
        int i = tid + it * 256;
        int row = i >> 5, f4 = i & 31;
        int g = rb + row;
        float4 v = make_float4(0.f, 0.f, 0.f, 0.f);
        if (g < n) v = *(const float4*)(X + (size_t)g * 128 + f4 * 4);

        __nv_bfloat16 hx = __float2bfloat16(v.x), hy = __float2bfloat16(v.y);
        __nv_bfloat16 hz = __float2bfloat16(v.z), hw = __float2bfloat16(v.w);
        __nv_bfloat16 lx = __float2bfloat16(v.x - __bfloat162float(hx));
        __nv_bfloat16 ly = __float2bfloat16(v.y - __bfloat162float(hy));
        __nv_bfloat16 lz = __float2bfloat16(v.z - __bfloat162float(hz));
        __nv_bfloat16 lw = __float2bfloat16(v.w - __bfloat162float(hw));

        uint2 hp, lp;
        hp.x = ((uint32_t)__bfloat16_as_ushort(hy) << 16) | __bfloat16_as_ushort(hx);
        hp.y = ((uint32_t)__bfloat16_as_ushort(hw) << 16) | __bfloat16_as_ushort(hz);
        lp.x = ((uint32_t)__bfloat16_as_ushort(ly) << 16) | __bfloat16_as_ushort(lx);
        lp.y = ((uint32_t)__bfloat16_as_ushort(lw) << 16) | __bfloat16_as_ushort(lz);
        int off = row * LDA + f4 * 8;
        *(uint2*)(a_hi + off) = hp;
        *(uint2*)(a_lo + off) = lp;
    }
    __syncthreads();

    float acc[MT][NT][4];
#pragma unroll
    for (int i = 0; i < MT; i++)
#pragma unroll
        for (int j = 0; j < NT; j++)
#pragma unroll
            for (int q = 0; q < 4; q++) acc[i][j][q] = 0.f;

    int lrow = (lane & 7) + ((lane >> 3) & 1) * 8;
    int lkh  = lane >> 4;

#pragma unroll
    for (int ks = 0; ks < 8; ks++) {
        int kb = ks * 16;
        uint32_t ah[MT][4], al[MT][4];
#pragma unroll
        for (int mt = 0; mt < MT; mt++) {
            uint32_t off = (uint32_t)((mbase + mt * 16 + lrow) * LDA + (kb + lkh * 8) * 2);
            ldmat_x4(ah[mt], sb_hi + off);
            ldmat_x4(al[mt], sb_lo + off);
        }
        uint32_t bh[NT][2], bl[NT][2];
#pragma unroll
        for (int j = 0; j < NT; j++) {
            int nn = nbase + j * 8 + (lane >> 2);
            int k0 = kb + (lane & 3) * 2;
            const __nv_bfloat16* ph = Bhi + (size_t)nn * 128 + k0;
            const __nv_bfloat16* pl = Blo + (size_t)nn * 128 + k0;
            bh[j][0] = *(const uint32_t*)ph;
            bh[j][1] = *(const uint32_t*)(ph + 8);
            bl[j][0] = *(const uint32_t*)pl;
            bl[j][1] = *(const uint32_t*)(pl + 8);
        }
#pragma unroll
        for (int mt = 0; mt < MT; mt++)
#pragma unroll
            for (int j = 0; j < NT; j++) {
                mma16816(acc[mt][j], ah[mt], bh[j]);
                mma16816(acc[mt][j], ah[mt], bl[j]);
                mma16816(acc[mt][j], al[mt], bh[j]);
            }
    }

    // ---- epilogue: scale by dinv[row], convert to fp16, store ----
#pragma unroll
    for (int mt = 0; mt < MT; mt++) {
        int r0 = rb + mbase + mt * 16 + (lane >> 2);
        int r1 = r0 + 8;
        float s0 = (r0 < n) ? dinv[r0] : 0.f;
        float s1 = (r1 < n) ? dinv[r1] : 0.f;
#pragma unroll
        for (int j = 0; j < NT; j++) {
            int col = nbase + j * 8 + (lane & 3) * 2;
            if (r0 < n) {
                __half2 h = __floats2half2_rn(acc[mt][j][0] * s0, acc[mt][j][1] * s0);
                *(__half2*)(T + (size_t)r0 * OUT + col) = h;
            }
            if (r1 < n) {
                __half2 h = __floats2half2_rn(acc[mt][j][2] * s1, acc[mt][j][3] * s1);
                *(__half2*)(T + (size_t)r1 * OUT + col) = h;
            }
        }
    }
}

// ---------------- aggregation:  Y[d] = act( dinv[d]*(T[d] + sum_{s} T[s]) + b ) ------
// one warp per destination node; lane owns C/32 contiguous columns (fp16 gather).
template <int C, bool RELU>
__global__ void __launch_bounds__(256)
k_agg(const __half* __restrict__ T, const float* __restrict__ bias,
      const float* __restrict__ dinv, const int* __restrict__ rowptr,
      const int* __restrict__ col, float* __restrict__ Y, int n) {
    constexpr int V = C / 32;          // halfs per lane: 4 or 2
    int w = (int)((blockIdx.x * 256 + threadIdx.x) >> 5);
    if (w >= n) return;
    int lane = threadIdx.x & 31;

    float acc[V];
    {
        const __half* p = T + (size_t)w * C + lane * V;
        if (V == 4) {
            uint2 u = *(const uint2*)p;
            float2 a = __half22float2(*(const __half2*)&u.x);
            float2 b = __half22float2(*(const __half2*)&u.y);
            acc[0] = a.x; acc[1] = a.y; acc[2] = b.x; acc[3] = b.y;
        } else {
            uint32_t u = *(const uint32_t*)p;
            float2 a = __half22float2(*(const __half2*)&u);
            acc[0] = a.x; acc[1] = a.y;
        }
    }

    int e = rowptr[w];
    int e1 = rowptr[w + 1];
    while (e < e1) {
        int m = min(32, e1 - e);
        int sidx = (lane < m) ? col[e + lane] : 0;
#pragma unroll 4
        for (int j = 0; j < m; j++) {
            int s = __shfl_sync(0xffffffffu, sidx, j);
            const __half* p = T + (size_t)s * C + lane * V;
            if (V == 4) {
                uint2 u = *(const uint2*)p;
                float2 a = __half22float2(*(const __half2*)&u.x);
                float2 b = __half22float2(*(const __half2*)&u.y);
                acc[0] += a.x; acc[1] += a.y; acc[2] += b.x; acc[3] += b.y;
            } else {
                uint32_t u = *(const uint32_t*)p;
                float2 a = __half22float2(*(const __half2*)&u);
                acc[0] += a.x; acc[1] += a.y;
            }
        }
        e += m;
    }

    float sc = dinv[w];
    float o[V];
    {
        const float* bp = bias + lane * V;
        if (V == 4) {
            float4 b = *(const float4*)bp;
            o[0] = fmaf(acc[0], sc, b.x);
            o[1] = fmaf(acc[1], sc, b.y);
            o[2] = fmaf(acc[2], sc, b.z);
            o[3] = fmaf(acc[3], sc, b.w);
        } else {
            float2 b = *(const float2*)bp;
            o[0] = fmaf(acc[0], sc, b.x);
            o[1] = fmaf(acc[1], sc, b.y);
        }
    }
    if (RELU) {
#pragma unroll
        for (int v = 0; v < V; v++) o[v] = fmaxf(o[v], 0.0f);
    }
    {
        float* p = Y + (size_t)w * C + lane * V;
        if (V == 4) *(float4*)p = make_float4(o[0], o[1], o[2], o[3]);
        else        *(float2*)p = make_float2(o[0], o[1]);
    }
}

// ---------------- launcher ----------------
extern "C" void kernel_launch(void* const* d_in, const int* in_sizes, int n_in,
                              void* d_out, int out_size) {
    const float* x  = (const float*)d_in[0];
    const int*   ei = (const int*)d_in[1];
    const float* W0 = (const float*)d_in[2];
    const float* b0 = (const float*)d_in[3];
    const float* W1 = (const float*)d_in[4];
    const float* b1 = (const float*)d_in[5];
    const float* W2 = (const float*)d_in[6];
    const float* b2 = (const float*)d_in[7];
    const float* W3 = (const float*)d_in[8];
    const float* b3 = (const float*)d_in[9];

    int N = in_sizes[0] / 128;
    int E = in_sizes[1] / 2;
    const int* src = ei;
    const int* dst = ei + E;

    float *Y, *dinv;
    __half* Th;
    int *cnt, *rowptr, *cursor, *colx, *part;
    __nv_bfloat16 *whi, *wlo;
    cudaGetSymbolAddress((void**)&Th, g_Th);
    cudaGetSymbolAddress((void**)&Y, g_Y);
    cudaGetSymbolAddress((void**)&dinv, g_dinv);
    cudaGetSymbolAddress((void**)&cnt, g_cnt);
    cudaGetSymbolAddress((void**)&rowptr, g_rowptr);
    cudaGetSymbolAddress((void**)&cursor, g_cursor);
    cudaGetSymbolAddress((void**)&colx, g_col);
    cudaGetSymbolAddress((void**)&part, g_part);
    cudaGetSymbolAddress((void**)&whi, g_whi);
    cudaGetSymbolAddress((void**)&wlo, g_wlo);

    constexpr int SMEM_A = 2 * 128 * 272;   // 69632 bytes
    cudaFuncSetAttribute(k_gemm_mma<128>, cudaFuncAttributeMaxDynamicSharedMemorySize, SMEM_A);
    cudaFuncSetAttribute(k_gemm_mma<64>,  cudaFuncAttributeMaxDynamicSharedMemorySize, SMEM_A);

    int nb = (N + 1023) / 1024;

    // CSR build
    k_zero <<<(N + 255) / 256, 256>>>(cnt, N);
    k_count<<<(E + 255) / 256, 256>>>(dst, cnt, E);
    k_bsum <<<nb, 256>>>(cnt, part, N);
    k_pscan<<<1, 128>>>(part, nb);
    k_wptr <<<nb, 256>>>(cnt, part, rowptr, cursor, dinv, N);
    k_fill <<<(E + 255) / 256, 256>>>(src, dst, cursor, colx, E);

    int gg = (N + 127) / 128;
    int ga = (N + 7) / 8;

    // layer 0
    k_wconv<<<(128 * 128 + 255) / 256, 256>>>(W0, whi, wlo, 128);
    k_gemm_mma<128><<<gg, 256, SMEM_A>>>(x, whi, wlo, dinv, Th, N);
    k_agg<128, true><<<ga, 256>>>(Th, b0, dinv, rowptr, colx, Y, N);
    // layer 1
    k_wconv<<<(128 * 128 + 255) / 256, 256>>>(W1, whi, wlo, 128);
    k_gemm_mma<128><<<gg, 256, SMEM_A>>>(Y, whi, wlo, dinv, Th, N);
    k_agg<128, true><<<ga, 256>>>(Th, b1, dinv, rowptr, colx, Y, N);
    // layer 2
    k_wconv<<<(128 * 128 + 255) / 256, 256>>>(W2, whi, wlo, 128);
    k_gemm_mma<128><<<gg, 256, SMEM_A>>>(Y, whi, wlo, dinv, Th, N);
    k_agg<128, true><<<ga, 256>>>(Th, b2, dinv, rowptr, colx, Y, N);
    // layer 3: H=128 -> O=64, no activation
    k_wconv<<<(128 * 64 + 255) / 256, 256>>>(W3, whi, wlo, 64);
    k_gemm_mma<64><<<gg, 256, SMEM_A>>>(Y, whi, wlo, dinv, Th, N);
    k_agg<64, false><<<ga, 256>>>(Th, b3, dinv, rowptr, colx, (float*)d_out, N);
}